// round 10
// baseline (speedup 1.0000x reference)
#include <cuda_runtime.h>

// Trilinear resize [4,128,128,128,2] f32 -> [4,192,192,192,2] f32, zoom=1.5.
// Exact 3-out-per-2-in periodicity, weights {1, 1/3, 2/3}.
// Persistent grid-stride version of the best skeleton (R3/R9):
//   - 1184 CTAs (148 SMs x 8), each loops over ~14 (b,zk,yk) tiles
//   - per-thread x-column setup hoisted out of the tile loop (tile-invariant)
//   - tile staged in smem via cooperative float4 loads
//   - thread = output x column: 18 LDS + y/z lerps + 27 coalesced __stcs

#define IN_D   128
#define OUT_D  192
#define NTILE  (4 * 64 * 64)   // 16384 (b, zk, yk) tiles
#define NCTA   1184            // 148 SMs x 8 resident CTAs

__device__ __forceinline__ float2 lerp2(float2 a, float2 b, float wa, float wb) {
    return make_float2(fmaf(a.x, wa, b.x * wb), fmaf(a.y, wa, b.y * wb));
}

__global__ __launch_bounds__(192) void resize_persist_kernel(
    const float2* __restrict__ in,   // [4,128,128,128] voxels (C=2 packed)
    float2* __restrict__ out)        // [4,192,192,192] voxels
{
    __shared__ float2 tile[9][IN_D];   // [zi*3+yi][x], 9216 B
    float4* tile4 = (float4*)tile;

    const int t = threadIdx.x;         // 0..191

    const float c13 = 1.0f / 3.0f;
    const float c23 = 2.0f / 3.0f;

    // ---- tile-invariant per-thread x-column setup (hoisted) ----
    const int q = t / 3;
    const int m = t - 3 * q;
    int xA, xB;
    float wA;
    if (m == 0)      { xA = 2 * q;     xB = xA;                       wA = 1.0f; }
    else if (m == 1) { xA = 2 * q;     xB = 2 * q + 1;                wA = c13;  }
    else             { xA = 2 * q + 1; xB = min(2 * q + 2, IN_D - 1); wA = c23;  }
    const float wB = 1.0f - wA;

    // loader-role constants (hoisted): 3 float4 chunks per thread
    const int lf4 = t & 63;            // float4 index within row
    const int lr0 = t >> 6;            // row for chunk 0 (rows 0..2)

    for (int tl = blockIdx.x; tl < NTILE; tl += NCTA) {
        const int yk = tl & 63;
        const int zk = (tl >> 6) & 63;
        const int b  = tl >> 12;

        const float4* in4 =
            (const float4*)(in + (size_t)b * (IN_D * IN_D * IN_D));

        // ---- Phase 1: cooperative float4 load of 9 input rows ----
        #pragma unroll
        for (int i = 0; i < 3; i++) {
            int r  = lr0 + 3 * i;      // 0..8
            int zi = r / 3;
            int yi = r - 3 * zi;
            int z = min(2 * zk + zi, IN_D - 1);
            int y = min(2 * yk + yi, IN_D - 1);
            tile4[r * 64 + lf4] = __ldg(in4 + ((size_t)z * IN_D + y) * 64 + lf4);
        }
        __syncthreads();

        // ---- Phase 2: x-lerp from smem + y-lerp per z plane ----
        float2 yl[3][3];               // [zi][yo]
        #pragma unroll
        for (int zi = 0; zi < 3; zi++) {
            float2 xv[3];
            #pragma unroll
            for (int yi = 0; yi < 3; yi++) {
                float2 a = tile[zi * 3 + yi][xA];
                float2 c = tile[zi * 3 + yi][xB];
                xv[yi] = lerp2(a, c, wA, wB);
            }
            yl[zi][0] = xv[0];
            yl[zi][1] = lerp2(xv[0], xv[1], c13, c23);
            yl[zi][2] = lerp2(xv[1], xv[2], c23, c13);
        }

        // ---- z-lerp + 27 coalesced streaming stores ----
        float2* obase = out +
            ((((size_t)b * OUT_D + 3 * zk) * OUT_D + 3 * yk) * OUT_D + t);
        #pragma unroll
        for (int yo = 0; yo < 3; yo++) {
            float2 v0 = yl[0][yo];
            float2 v1 = yl[1][yo];
            float2 v2 = yl[2][yo];
            __stcs(obase + (size_t)(0 * OUT_D + yo) * OUT_D, v0);
            __stcs(obase + (size_t)(1 * OUT_D + yo) * OUT_D,
                   lerp2(v0, v1, c13, c23));
            __stcs(obase + (size_t)(2 * OUT_D + yo) * OUT_D,
                   lerp2(v1, v2, c23, c13));
        }

        // protect smem before next iteration's load overwrites it
        __syncthreads();
    }
}

extern "C" void kernel_launch(void* const* d_in, const int* in_sizes, int n_in,
                              void* d_out, int out_size) {
    const float2* in = (const float2*)d_in[0];
    float2* out = (float2*)d_out;

    resize_persist_kernel<<<NCTA, 192>>>(in, out);
}

// round 11
// speedup vs baseline: 1.0446x; 1.0446x over previous
#include <cuda_runtime.h>
#include <cstdint>

// Trilinear resize [4,128,128,128,2] f32 -> [4,192,192,192,2] f32, zoom=1.5.
// Exact 3-out-per-2-in periodicity, weights {1, 1/3, 2/3}.
// Persistent (2048 CTAs x 8 tiles) with DOUBLE-BUFFERED cp.async prefetch:
// tile i+1 streams into smem buffer 1-c while tile i is computed/stored from
// buffer c. Inner body = proven R9: thread = output x column, 18 LDS,
// y/z lerps in registers, 27 perfectly coalesced __stcs.

#define IN_D   128
#define OUT_D  192
#define NTILE  (4 * 64 * 64)   // 16384 tiles (b, zk, yk)
#define NCTA   2048            // 16384 / 2048 = exactly 8 tiles per CTA
#define BUF_BYTES (9 * IN_D * 8)   // 9216 B per buffer

__device__ __forceinline__ float2 lerp2(float2 a, float2 b, float wa, float wb) {
    return make_float2(fmaf(a.x, wa, b.x * wb), fmaf(a.y, wa, b.y * wb));
}

__global__ __launch_bounds__(192) void resize_pipe_kernel(
    const float2* __restrict__ in,   // [4,128,128,128] voxels (C=2 packed)
    float2* __restrict__ out)        // [4,192,192,192] voxels
{
    __shared__ float2 tile[2][9][IN_D];   // 2 x 9216 B

    const int t = threadIdx.x;            // 0..191

    const float c13 = 1.0f / 3.0f;
    const float c23 = 2.0f / 3.0f;

    // ---- tile-invariant per-thread x-column setup ----
    const int q = t / 3;
    const int m = t - 3 * q;
    int xA, xB;
    float wA;
    if (m == 0)      { xA = 2 * q;     xB = xA;                       wA = 1.0f; }
    else if (m == 1) { xA = 2 * q;     xB = 2 * q + 1;                wA = c13;  }
    else             { xA = 2 * q + 1; xB = min(2 * q + 2, IN_D - 1); wA = c23;  }
    const float wB = 1.0f - wA;

    // loader-role constants: 3 float4 chunks per thread per tile
    const int lf4 = t & 63;               // float4 index within row
    const int lr0 = t >> 6;               // base row (0..2)

    uint32_t sbase;
    asm("{ .reg .u64 a; cvta.to.shared.u64 a, %1; cvt.u32.u64 %0, a; }"
        : "=r"(sbase) : "l"(tile));

    // issue async copy of one tile into buffer `buf`; always commits a group
    auto issue = [&](int tl, int buf) {
        if (tl < NTILE) {
            int yk = tl & 63;
            int zk = (tl >> 6) & 63;
            int b  = tl >> 12;
            const float4* in4 =
                (const float4*)(in + (size_t)b * (IN_D * IN_D * IN_D));
            #pragma unroll
            for (int i = 0; i < 3; i++) {
                int r  = lr0 + 3 * i;     // 0..8
                int zi = r / 3;
                int yi = r - 3 * zi;
                int z = min(2 * zk + zi, IN_D - 1);
                int y = min(2 * yk + yi, IN_D - 1);
                uint32_t dst = sbase + buf * BUF_BYTES + (r * 64 + lf4) * 16;
                const float4* g = in4 + ((size_t)z * IN_D + y) * 64 + lf4;
                asm volatile("cp.async.cg.shared.global [%0], [%1], 16;"
                             :: "r"(dst), "l"(g));
            }
        }
        asm volatile("cp.async.commit_group;");
    };

    const int tl0 = blockIdx.x;
    issue(tl0, 0);                 // tile i   -> buf 0
    issue(tl0 + NCTA, 1);          // tile i+1 -> buf 1

    int c = 0;
    for (int tl = tl0; tl < NTILE; tl += NCTA) {
        // wait until the oldest pending group (current tile) has landed
        asm volatile("cp.async.wait_group 1;");
        __syncthreads();

        const int yk = tl & 63;
        const int zk = (tl >> 6) & 63;
        const int b  = tl >> 12;

        // ---- x-lerp from smem + y-lerp per z plane ----
        float2 yl[3][3];
        #pragma unroll
        for (int zi = 0; zi < 3; zi++) {
            float2 xv[3];
            #pragma unroll
            for (int yi = 0; yi < 3; yi++) {
                float2 a = tile[c][zi * 3 + yi][xA];
                float2 cc = tile[c][zi * 3 + yi][xB];
                xv[yi] = lerp2(a, cc, wA, wB);
            }
            yl[zi][0] = xv[0];
            yl[zi][1] = lerp2(xv[0], xv[1], c13, c23);
            yl[zi][2] = lerp2(xv[1], xv[2], c23, c13);
        }

        // ---- z-lerp + 27 coalesced streaming stores ----
        float2* obase = out +
            ((((size_t)b * OUT_D + 3 * zk) * OUT_D + 3 * yk) * OUT_D + t);
        #pragma unroll
        for (int yo = 0; yo < 3; yo++) {
            float2 v0 = yl[0][yo];
            float2 v1 = yl[1][yo];
            float2 v2 = yl[2][yo];
            __stcs(obase + (size_t)(0 * OUT_D + yo) * OUT_D, v0);
            __stcs(obase + (size_t)(1 * OUT_D + yo) * OUT_D,
                   lerp2(v0, v1, c13, c23));
            __stcs(obase + (size_t)(2 * OUT_D + yo) * OUT_D,
                   lerp2(v1, v2, c23, c13));
        }

        __syncthreads();           // everyone done reading buf c
        issue(tl + 2 * NCTA, c);   // prefetch tile i+2 into the freed buffer
        c ^= 1;
    }
}

extern "C" void kernel_launch(void* const* d_in, const int* in_sizes, int n_in,
                              void* d_out, int out_size) {
    const float2* in = (const float2*)d_in[0];
    float2* out = (float2*)d_out;

    resize_pipe_kernel<<<NCTA, 192>>>(in, out);
}

// round 12
// speedup vs baseline: 1.1352x; 1.0868x over previous
#include <cuda_runtime.h>

// Trilinear resize [4,128,128,128,2] f32 -> [4,192,192,192,2] f32, zoom=1.5.
// FINAL (best of 9 structural variants; ~98% of measured streaming-write
// DRAM ceiling on GB300).
//
// zoom=1.5 is exactly 3 outputs per 2 inputs with fixed weights {1, 1/3, 2/3}
// per axis (offset 0 is an exact copy). Block = (b, zk, yk): stages the input
// strip [3z][3y][128x] in smem via a coalesced cooperative load; each thread
// owns one output x column, does the x-lerp from smem and the y/z lerps in
// registers, then issues 27 perfectly coalesced STG.64 (9 contiguous
// 1536-byte output rows per block). 16384 independent CTAs at ~85% occupancy
// form the load/store pipeline that hides all latency.

#define IN_D  128
#define OUT_D 192

__device__ __forceinline__ float2 lerp2(float2 a, float2 b, float wa, float wb) {
    return make_float2(fmaf(a.x, wa, b.x * wb), fmaf(a.y, wa, b.y * wb));
}

__global__ __launch_bounds__(192) void resize_smem_kernel(
    const float2* __restrict__ in,   // [4,128,128,128] voxels (C=2 packed)
    float2* __restrict__ out)        // [4,192,192,192] voxels
{
    __shared__ float2 tile[9][IN_D];   // [zi*3+yi][x], 9216 B

    const int blk = blockIdx.x;
    const int yk = blk & 63;
    const int zk = (blk >> 6) & 63;
    const int b  = blk >> 12;

    const int tid = threadIdx.x;       // 0..191

    const float2* base = in + (size_t)b * (IN_D * IN_D * IN_D);

    // ---- Phase 1: cooperative coalesced load of 9 input rows (1152 float2) ----
    #pragma unroll
    for (int i = 0; i < 6; i++) {
        int idx = i * 192 + tid;       // 0..1151
        int x = idx & 127;
        int r = idx >> 7;              // 0..8
        int zi = r / 3;
        int yi = r - 3 * zi;
        int z = min(2 * zk + zi, IN_D - 1);
        int y = min(2 * yk + yi, IN_D - 1);
        tile[r][x] = __ldg(base + ((size_t)z * IN_D + y) * IN_D + x);
    }
    __syncthreads();

    // ---- Phase 2: per-thread x-lerp, then y/z lerp in registers ----
    const float c13 = 1.0f / 3.0f;
    const float c23 = 2.0f / 3.0f;

    const int k  = tid / 3;            // output micro-block index along x
    const int xo = tid - 3 * k;        // 0,1,2 within micro-block

    // corner indices + weights for this output x
    int xA, xB;
    float wA;
    if (xo == 0)      { xA = 2 * k;     xB = xA;                     wA = 1.0f; }
    else if (xo == 1) { xA = 2 * k;     xB = 2 * k + 1;              wA = c13;  }
    else              { xA = 2 * k + 1; xB = min(2 * k + 2, IN_D-1); wA = c23;  }
    const float wB = 1.0f - wA;

    float2 xl[9];                      // x-lerped, [zi*3+yi]
    #pragma unroll
    for (int r = 0; r < 9; r++) {
        float2 a = tile[r][xA];
        float2 c = tile[r][xB];
        xl[r] = lerp2(a, c, wA, wB);
    }

    // y-lerp: per z-plane, 3 input y -> 3 output y
    float2 yl[3][3];                   // [zi][yo]
    #pragma unroll
    for (int zi = 0; zi < 3; zi++) {
        float2 v0 = xl[3 * zi + 0];
        float2 v1 = xl[3 * zi + 1];
        float2 v2 = xl[3 * zi + 2];
        yl[zi][0] = v0;
        yl[zi][1] = lerp2(v0, v1, c13, c23);
        yl[zi][2] = lerp2(v1, v2, c23, c13);
    }

    // z-lerp + coalesced stores (thread t writes column t of each 192-row)
    size_t obase = (((size_t)b * OUT_D + 3 * zk) * OUT_D + 3 * yk) * OUT_D + tid;
    #pragma unroll
    for (int yo = 0; yo < 3; yo++) {
        float2 v0 = yl[0][yo];
        float2 v1 = yl[1][yo];
        float2 v2 = yl[2][yo];
        out[obase + (size_t)(0 * OUT_D + yo) * OUT_D] = v0;
        out[obase + (size_t)(1 * OUT_D + yo) * OUT_D] = lerp2(v0, v1, c13, c23);
        out[obase + (size_t)(2 * OUT_D + yo) * OUT_D] = lerp2(v1, v2, c23, c13);
    }
}

extern "C" void kernel_launch(void* const* d_in, const int* in_sizes, int n_in,
                              void* d_out, int out_size) {
    const float2* in = (const float2*)d_in[0];
    float2* out = (float2*)d_out;

    int blocks = 4 * 64 * 64;   // (b, zk, yk) = 16384
    resize_smem_kernel<<<blocks, 192>>>(in, out);
}